// round 1
// baseline (speedup 1.0000x reference)
#include <cuda_runtime.h>
#include <cuda_bf16.h>
#include <math.h>

// Problem constants
#define BATCH 4
#define SEQ   1024
#define QDIM  512
#define NH    8
#define HD    64
#define BH    (BATCH*NH)          // 32
#define PROJ_ELEMS (BATCH*NH*SEQ*HD)  // 2,097,152
#define OUT_ELEMS  (BATCH*SEQ*HD)     // 262,144 (output part), attn follows

// Scratch ([b,h,l,d] layout, fp32)
__device__ float g_q[PROJ_ELEMS];
__device__ float g_k[PROJ_ELEMS];
__device__ float g_v[PROJ_ELEMS];
__device__ float g_ctx[PROJ_ELEMS];

// ---------------------------------------------------------------------------
// smem tile loaders: 64x64 fp32 tiles, 256 threads
// ---------------------------------------------------------------------------

// Load 64x64 tile transposed: dst[col][row]  (for reduction-along-col GEMMs)
__device__ __forceinline__ void load_tile_T(const float* __restrict__ src, int stride,
                                            float (*dst)[68], int t) {
    int r = t & 63;          // source row
    int q = t >> 6;          // col quarter: 0..3 -> cols q*16..q*16+15
    const float* s = src + r * stride + q * 16;
#pragma unroll
    for (int c0 = 0; c0 < 16; c0 += 4) {
        float4 v = *(const float4*)(s + c0);
        int c = q * 16 + c0;
        dst[c + 0][r] = v.x;
        dst[c + 1][r] = v.y;
        dst[c + 2][r] = v.z;
        dst[c + 3][r] = v.w;
    }
}

// Load 64x64 tile natural: dst[row][col]
__device__ __forceinline__ void load_tile(const float* __restrict__ src, int stride,
                                          float (*dst)[68], int t) {
    int r = t >> 2;          // 0..63
    int c4 = t & 3;          // col quarter
    const float* s = src + r * stride + c4 * 16;
#pragma unroll
    for (int c0 = 0; c0 < 16; c0 += 4) {
        float4 v = *(const float4*)(s + c0);
        *(float4*)(&dst[r][c4 * 16 + c0]) = v;
    }
}

#define MICRO_FMA(a, b)                                              \
    acc[0][0] += a.x * b.x; acc[0][1] += a.x * b.y;                  \
    acc[0][2] += a.x * b.z; acc[0][3] += a.x * b.w;                  \
    acc[1][0] += a.y * b.x; acc[1][1] += a.y * b.y;                  \
    acc[1][2] += a.y * b.z; acc[1][3] += a.y * b.w;                  \
    acc[2][0] += a.z * b.x; acc[2][1] += a.z * b.y;                  \
    acc[2][2] += a.z * b.z; acc[2][3] += a.z * b.w;                  \
    acc[3][0] += a.w * b.x; acc[3][1] += a.w * b.y;                  \
    acc[3][2] += a.w * b.z; acc[3][3] += a.w * b.w;

// ---------------------------------------------------------------------------
// Kernel 1: input projections  Y = X @ W^T + bias  -> scratch in [b,h,l,d]
// X: [4096, 512], W: [512, 512] (row-major [out,in]), grid (8 n-tiles, 64 m-tiles)
// ---------------------------------------------------------------------------
__global__ __launch_bounds__(256) void proj_kernel(const float* __restrict__ X,
                                                   const float* __restrict__ W,
                                                   const float* __restrict__ bias,
                                                   int sel) {
    __shared__ float XsT[64][68];   // [k][m]
    __shared__ float WsT[64][68];   // [k][n]
    float* dst = (sel == 0) ? g_q : (sel == 1) ? g_k : g_v;

    int t = threadIdx.x;
    int n0 = blockIdx.x * 64;       // h = blockIdx.x
    int m0 = blockIdx.y * 64;
    int ty = t >> 4, tx = t & 15;

    float acc[4][4] = {};
    for (int k0 = 0; k0 < QDIM; k0 += 64) {
        __syncthreads();
        load_tile_T(X + m0 * QDIM + k0, QDIM, XsT, t);
        load_tile_T(W + n0 * QDIM + k0, QDIM, WsT, t);
        __syncthreads();
#pragma unroll 16
        for (int kk = 0; kk < 64; kk++) {
            float4 a = *(const float4*)(&XsT[kk][ty * 4]);
            float4 b = *(const float4*)(&WsT[kk][tx * 4]);
            MICRO_FMA(a, b);
        }
    }

    int b = m0 >> 10;
    int l0 = m0 & 1023;
    int h = blockIdx.x;
    float4 b4 = *(const float4*)(bias + n0 + tx * 4);
    float* outBase = dst + (size_t)(b * NH + h) * SEQ * HD;
#pragma unroll
    for (int i = 0; i < 4; i++) {
        float4 r;
        r.x = acc[i][0] + b4.x;
        r.y = acc[i][1] + b4.y;
        r.z = acc[i][2] + b4.z;
        r.w = acc[i][3] + b4.w;
        *(float4*)(outBase + (size_t)(l0 + ty * 4 + i) * HD + tx * 4) = r;
    }
}

// ---------------------------------------------------------------------------
// Kernel 2: raw scores  S[bh][q][k] = 0.5 * Q[q,:]·K[k,:]  -> attn region
// grid (16 k-tiles, 16 q-tiles, 32 bh)
// ---------------------------------------------------------------------------
__global__ __launch_bounds__(256) void scores_kernel(float* __restrict__ attn) {
    __shared__ float QsT[64][68];   // [d][q]
    __shared__ float KsT[64][68];   // [d][k]
    int t = threadIdx.x;
    int kt = blockIdx.x, qt = blockIdx.y, bh = blockIdx.z;

    const float* Qbase = g_q + (size_t)(bh * SEQ + qt * 64) * HD;
    const float* Kbase = g_k + (size_t)(bh * SEQ + kt * 64) * HD;
    load_tile_T(Qbase, HD, QsT, t);
    load_tile_T(Kbase, HD, KsT, t);
    __syncthreads();

    int ty = t >> 4, tx = t & 15;
    float acc[4][4] = {};
#pragma unroll 16
    for (int d = 0; d < 64; d++) {
        float4 a = *(const float4*)(&QsT[d][ty * 4]);
        float4 b = *(const float4*)(&KsT[d][tx * 4]);
        MICRO_FMA(a, b);
    }

    float* out = attn + (size_t)(bh * SEQ + qt * 64 + ty * 4) * SEQ + kt * 64 + tx * 4;
#pragma unroll
    for (int i = 0; i < 4; i++) {
        float4 r;
        r.x = acc[i][0] * 0.5f;   // 1/sqrt(batch)
        r.y = acc[i][1] * 0.5f;
        r.z = acc[i][2] * 0.5f;
        r.w = acc[i][3] * 0.5f;
        *(float4*)(out + (size_t)i * SEQ) = r;
    }
}

// ---------------------------------------------------------------------------
// Kernel 3: in-place row softmax over attn rows (32768 rows x 1024)
// ---------------------------------------------------------------------------
__global__ __launch_bounds__(256) void softmax_kernel(float* __restrict__ attn) {
    __shared__ float red[16];
    float* p = attn + (size_t)blockIdx.x * SEQ;
    int t = threadIdx.x;
    float4 v = *(float4*)(p + t * 4);

    float mx = fmaxf(fmaxf(v.x, v.y), fmaxf(v.z, v.w));
#pragma unroll
    for (int o = 16; o; o >>= 1) mx = fmaxf(mx, __shfl_xor_sync(0xffffffffu, mx, o));
    if ((t & 31) == 0) red[t >> 5] = mx;
    __syncthreads();
    mx = red[0];
#pragma unroll
    for (int i = 1; i < 8; i++) mx = fmaxf(mx, red[i]);

    v.x = __expf(v.x - mx);
    v.y = __expf(v.y - mx);
    v.z = __expf(v.z - mx);
    v.w = __expf(v.w - mx);
    float sum = (v.x + v.y) + (v.z + v.w);
#pragma unroll
    for (int o = 16; o; o >>= 1) sum += __shfl_xor_sync(0xffffffffu, sum, o);
    if ((t & 31) == 0) red[8 + (t >> 5)] = sum;
    __syncthreads();
    sum = 0.f;
#pragma unroll
    for (int i = 0; i < 8; i++) sum += red[8 + i];

    float inv = 1.0f / sum;
    v.x *= inv; v.y *= inv; v.z *= inv; v.w *= inv;
    *(float4*)(p + t * 4) = v;
}

// ---------------------------------------------------------------------------
// Kernel 4: context  C[bh][k][d] = sum_q A[bh][q][k] * V[bh][q][d]
// grid (16 k-tiles, 32 bh)
// ---------------------------------------------------------------------------
__global__ __launch_bounds__(256) void context_kernel(const float* __restrict__ attn) {
    __shared__ float As[64][68];   // [q][k]
    __shared__ float Vs[64][68];   // [q][d]
    int t = threadIdx.x;
    int kt = blockIdx.x, bh = blockIdx.y;
    int ty = t >> 4, tx = t & 15;

    const float* Abase = attn + (size_t)bh * SEQ * SEQ + kt * 64;
    const float* Vbase = g_v + (size_t)bh * SEQ * HD;

    float acc[4][4] = {};
    for (int q0 = 0; q0 < SEQ; q0 += 64) {
        __syncthreads();
        load_tile(Abase + (size_t)q0 * SEQ, SEQ, As, t);
        load_tile(Vbase + (size_t)q0 * HD, HD, Vs, t);
        __syncthreads();
#pragma unroll 16
        for (int q = 0; q < 64; q++) {
            float4 a = *(const float4*)(&As[q][ty * 4]);
            float4 b = *(const float4*)(&Vs[q][tx * 4]);
            MICRO_FMA(a, b);
        }
    }

    float* out = g_ctx + (size_t)(bh * SEQ + kt * 64 + ty * 4) * HD + tx * 4;
#pragma unroll
    for (int i = 0; i < 4; i++) {
        float4 r;
        r.x = acc[i][0]; r.y = acc[i][1]; r.z = acc[i][2]; r.w = acc[i][3];
        *(float4*)(out + (size_t)i * HD) = r;
    }
}

// ---------------------------------------------------------------------------
// Kernel 5: output = ctx_flat[4096,512] @ wp^T[512,64] + bp -> out[4096,64]
// ctx_flat[m=(b,l)][kk=(h,dd)] lives at g_ctx[((b*8+h)*1024+l)*64+dd]
// grid: 64 m-tiles
// ---------------------------------------------------------------------------
__global__ __launch_bounds__(256) void outproj_kernel(const float* __restrict__ W,
                                                      const float* __restrict__ bias,
                                                      float* __restrict__ out) {
    __shared__ float AsT[64][68];   // [kk][m]
    __shared__ float WsT[64][68];   // [kk][n]
    int t = threadIdx.x;
    int m0 = blockIdx.x * 64;
    int b = m0 >> 10;
    int l0 = m0 & 1023;
    int ty = t >> 4, tx = t & 15;

    float acc[4][4] = {};
    for (int k0 = 0; k0 < QDIM; k0 += 64) {
        int h = k0 >> 6;   // whole 64-chunk lies in one head
        __syncthreads();
        load_tile_T(g_ctx + (size_t)(b * NH + h) * SEQ * HD + (size_t)l0 * HD, HD, AsT, t);
        load_tile_T(W + k0, QDIM, WsT, t);   // wp rows n=0..63, cols k0..k0+63
        __syncthreads();
#pragma unroll 16
        for (int kk = 0; kk < 64; kk++) {
            float4 a = *(const float4*)(&AsT[kk][ty * 4]);
            float4 b4 = *(const float4*)(&WsT[kk][tx * 4]);
            MICRO_FMA(a, b4);
        }
    }

    float4 bp4 = *(const float4*)(bias + tx * 4);
#pragma unroll
    for (int i = 0; i < 4; i++) {
        float4 r;
        r.x = acc[i][0] + bp4.x;
        r.y = acc[i][1] + bp4.y;
        r.z = acc[i][2] + bp4.z;
        r.w = acc[i][3] + bp4.w;
        *(float4*)(out + (size_t)(m0 + ty * 4 + i) * HD + tx * 4) = r;
    }
}

// ---------------------------------------------------------------------------
// Launch
// ---------------------------------------------------------------------------
extern "C" void kernel_launch(void* const* d_in, const int* in_sizes, int n_in,
                              void* d_out, int out_size) {
    const float* q  = (const float*)d_in[0];
    const float* k  = (const float*)d_in[1];
    const float* v  = (const float*)d_in[2];
    const float* wq = (const float*)d_in[3];
    const float* bq = (const float*)d_in[4];
    const float* wk = (const float*)d_in[5];
    const float* bk = (const float*)d_in[6];
    const float* wv = (const float*)d_in[7];
    const float* bv = (const float*)d_in[8];
    const float* wp = (const float*)d_in[9];
    const float* bp = (const float*)d_in[10];

    float* out  = (float*)d_out;             // [4,1024,64]
    float* attn = out + OUT_ELEMS;           // [4,8,1024,1024]

    dim3 projGrid(NH, (BATCH * SEQ) / 64);   // (8, 64)
    proj_kernel<<<projGrid, 256>>>(q, wq, bq, 0);
    proj_kernel<<<projGrid, 256>>>(k, wk, bk, 1);
    proj_kernel<<<projGrid, 256>>>(v, wv, bv, 2);

    dim3 scoreGrid(SEQ / 64, SEQ / 64, BH);  // (16, 16, 32)
    scores_kernel<<<scoreGrid, 256>>>(attn);

    softmax_kernel<<<BH * SEQ, 256>>>(attn); // 32768 rows

    dim3 ctxGrid(SEQ / 64, BH);              // (16, 32)
    context_kernel<<<ctxGrid, 256>>>(attn);

    outproj_kernel<<<(BATCH * SEQ) / 64, 256>>>(wp, bp, out);
}

// round 2
// speedup vs baseline: 1.6312x; 1.6312x over previous
#include <cuda_runtime.h>
#include <math.h>
#include <stdint.h>

#define BATCH 4
#define SEQ   1024
#define QDIM  512
#define NH    8
#define HD    64
#define OUT_ELEMS  (BATCH*SEQ*HD)
#define PROJ_ELEMS (BATCH*NH*SEQ*HD)

__device__ float g_q[PROJ_ELEMS];
__device__ float g_k[PROJ_ELEMS];
__device__ float g_v[PROJ_ELEMS];
__device__ float g_ctx[PROJ_ELEMS];

// ---------------------------------------------------------------------------
// tf32 helpers
// ---------------------------------------------------------------------------
__device__ __forceinline__ uint32_t f2tf(float x){
    uint32_t r; asm("cvt.rna.tf32.f32 %0, %1;" : "=r"(r) : "f"(x)); return r;
}
__device__ __forceinline__ void split_tf(float x, uint32_t& hi, uint32_t& lo){
    hi = f2tf(x);
    lo = f2tf(x - __uint_as_float(hi));
}
__device__ __forceinline__ void mma8(float c[4], const uint32_t a[4], const uint32_t b[2]){
    asm volatile("mma.sync.aligned.m16n8k8.row.col.f32.tf32.tf32.f32 "
        "{%0,%1,%2,%3},{%4,%5,%6,%7},{%8,%9},{%0,%1,%2,%3};"
        : "+f"(c[0]),"+f"(c[1]),"+f"(c[2]),"+f"(c[3])
        : "r"(a[0]),"r"(a[1]),"r"(a[2]),"r"(a[3]),"r"(b[0]),"r"(b[1]));
}

// fragment loaders. Layouts:
//   lda4 / ldb2  : smem is [row][kred] (A row-major, B n-major)
//   lda4T / ldb2T: smem is [kred][col] (operand stored k-major)
__device__ __forceinline__ void lda4(const float* S, int stride, int row0, int kc, float a[4]){
    int lane = threadIdx.x & 31; int gr = lane>>2, c = lane&3;
    const float* p = S + (row0+gr)*stride + kc + c;
    a[0]=p[0]; a[1]=p[8*stride]; a[2]=p[4]; a[3]=p[8*stride+4];
}
__device__ __forceinline__ void ldb2(const float* S, int stride, int n0, int kc, float b[2]){
    int lane = threadIdx.x & 31;
    const float* p = S + (n0+(lane>>2))*stride + kc + (lane&3);
    b[0]=p[0]; b[1]=p[4];
}
__device__ __forceinline__ void lda4T(const float* S, int stride, int row0, int kc, float a[4]){
    int lane = threadIdx.x & 31; int gr = lane>>2, c = lane&3;
    const float* p = S + (kc+c)*stride + row0 + gr;
    a[0]=p[0]; a[1]=p[8]; a[2]=p[4*stride]; a[3]=p[4*stride+8];
}
__device__ __forceinline__ void ldb2T(const float* S, int stride, int n0, int kc, float b[2]){
    int lane = threadIdx.x & 31;
    const float* p = S + (kc+(lane&3))*stride + n0 + (lane>>2);
    b[0]=p[0]; b[1]=p[4*stride];
}

// ---------------------------------------------------------------------------
// Kernel 1: projections  Y = X @ W^T + b  (3xTF32)  -> [b,h,l,d] scratch
// block tile 128m x 64n (n block = one head), 8 warps 4x2, warp 32x32
// ---------------------------------------------------------------------------
__global__ __launch_bounds__(256) void proj_kernel(const float* __restrict__ X,
        const float* __restrict__ W, const float* __restrict__ bias, int sel){
    __shared__ float Xs[128][36];
    __shared__ float Ws[64][36];
    float* dst = sel==0 ? g_q : sel==1 ? g_k : g_v;
    int tid = threadIdx.x;
    int h = blockIdx.x, n0 = h*64;
    int m0 = blockIdx.y*128;
    int w = tid>>5, wm = w>>1, wn = w&1;
    int lane = tid&31, gr = lane>>2, c2 = (lane&3)*2;

    float acc[2][4][4] = {};
    for (int k0=0; k0<QDIM; k0+=32){
        __syncthreads();
        #pragma unroll
        for (int i=0;i<4;i++){ int lin=tid+i*256; int r=lin>>3, cc=(lin&7)*4;
            *(float4*)&Xs[r][cc] = *(const float4*)(X + (size_t)(m0+r)*QDIM + k0 + cc); }
        #pragma unroll
        for (int i=0;i<2;i++){ int lin=tid+i*256; int r=lin>>3, cc=(lin&7)*4;
            *(float4*)&Ws[r][cc] = *(const float4*)(W + (size_t)(n0+r)*QDIM + k0 + cc); }
        __syncthreads();
        #pragma unroll
        for (int kc=0; kc<32; kc+=8){
            uint32_t ah[2][4], al[2][4];
            #pragma unroll
            for (int mi=0;mi<2;mi++){
                float af[4]; lda4(&Xs[0][0],36, wm*32+mi*16, kc, af);
                #pragma unroll
                for (int j=0;j<4;j++) split_tf(af[j], ah[mi][j], al[mi][j]);
            }
            #pragma unroll
            for (int ni=0;ni<4;ni++){
                float bf[2]; uint32_t bh_[2], bl_[2];
                ldb2(&Ws[0][0],36, wn*32+ni*8, kc, bf);
                split_tf(bf[0],bh_[0],bl_[0]); split_tf(bf[1],bh_[1],bl_[1]);
                #pragma unroll
                for (int mi=0;mi<2;mi++){
                    mma8(acc[mi][ni], ah[mi], bh_);
                    mma8(acc[mi][ni], ah[mi], bl_);
                    mma8(acc[mi][ni], al[mi], bh_);
                }
            }
        }
    }
    int b = m0>>10, l0 = m0&1023;
    float* base = dst + (size_t)(b*NH+h)*SEQ*HD;
    #pragma unroll
    for (int mi=0;mi<2;mi++)
    #pragma unroll
    for (int ni=0;ni<4;ni++){
        int row = l0 + wm*32 + mi*16 + gr;
        int col = wn*32 + ni*8 + c2;
        float2 bb = *(const float2*)(bias + n0 + col);
        float2 v0 = {acc[mi][ni][0]+bb.x, acc[mi][ni][1]+bb.y};
        float2 v1 = {acc[mi][ni][2]+bb.x, acc[mi][ni][3]+bb.y};
        *(float2*)(base + (size_t)row*HD + col) = v0;
        *(float2*)(base + (size_t)(row+8)*HD + col) = v1;
    }
}

// ---------------------------------------------------------------------------
// Kernel 2: scores S = 0.5 * Q K^T (3xTF32) -> attn region (raw, pre-softmax)
// block tile 128q x 128k, warps 2x4, warp 64x32
// ---------------------------------------------------------------------------
__global__ __launch_bounds__(256) void scores_kernel(float* __restrict__ attn){
    __shared__ float Qs[128][36];
    __shared__ float Ks[128][36];
    int tid = threadIdx.x;
    int kb = blockIdx.x*128, q0 = blockIdx.y*128, bh = blockIdx.z;
    int w = tid>>5, wq = w>>2, wk = w&3;
    int lane = tid&31, gr = lane>>2, c2 = (lane&3)*2;
    const float* Qg = g_q + (size_t)(bh*SEQ + q0)*HD;
    const float* Kg = g_k + (size_t)(bh*SEQ + kb)*HD;

    float acc[4][4][4] = {};
    #pragma unroll
    for (int dt=0; dt<2; dt++){
        int d0 = dt*32;
        __syncthreads();
        #pragma unroll
        for (int i=0;i<4;i++){ int lin=tid+i*256; int r=lin>>3, cc=(lin&7)*4;
            *(float4*)&Qs[r][cc] = *(const float4*)(Qg + (size_t)r*HD + d0 + cc);
            *(float4*)&Ks[r][cc] = *(const float4*)(Kg + (size_t)r*HD + d0 + cc); }
        __syncthreads();
        #pragma unroll
        for (int kc=0; kc<32; kc+=8){
            uint32_t ah[4][4], al[4][4];
            #pragma unroll
            for (int mi=0;mi<4;mi++){
                float af[4]; lda4(&Qs[0][0],36, wq*64+mi*16, kc, af);
                #pragma unroll
                for (int j=0;j<4;j++) split_tf(af[j], ah[mi][j], al[mi][j]);
            }
            #pragma unroll
            for (int ni=0;ni<4;ni++){
                float bf[2]; uint32_t bh_[2], bl_[2];
                ldb2(&Ks[0][0],36, wk*32+ni*8, kc, bf);
                split_tf(bf[0],bh_[0],bl_[0]); split_tf(bf[1],bh_[1],bl_[1]);
                #pragma unroll
                for (int mi=0;mi<4;mi++){
                    mma8(acc[mi][ni], ah[mi], bh_);
                    mma8(acc[mi][ni], ah[mi], bl_);
                    mma8(acc[mi][ni], al[mi], bh_);
                }
            }
        }
    }
    float* Ab = attn + (size_t)bh*SEQ*SEQ;
    #pragma unroll
    for (int mi=0;mi<4;mi++)
    #pragma unroll
    for (int ni=0;ni<4;ni++){
        int row = q0 + wq*64 + mi*16 + gr;
        int col = kb + wk*32 + ni*8 + c2;
        float2 v0 = {acc[mi][ni][0]*0.5f, acc[mi][ni][1]*0.5f};
        float2 v1 = {acc[mi][ni][2]*0.5f, acc[mi][ni][3]*0.5f};
        *(float2*)(Ab + (size_t)row*SEQ + col) = v0;
        *(float2*)(Ab + (size_t)(row+8)*SEQ + col) = v1;
    }
}

// ---------------------------------------------------------------------------
// Kernel 3: in-place row softmax (32768 rows x 1024)
// ---------------------------------------------------------------------------
__global__ __launch_bounds__(256) void softmax_kernel(float* __restrict__ attn){
    __shared__ float red[16];
    float* p = attn + (size_t)blockIdx.x * SEQ;
    int t = threadIdx.x;
    float4 v = *(float4*)(p + t*4);

    float mx = fmaxf(fmaxf(v.x,v.y), fmaxf(v.z,v.w));
    #pragma unroll
    for (int o=16;o;o>>=1) mx = fmaxf(mx, __shfl_xor_sync(0xffffffffu, mx, o));
    if ((t&31)==0) red[t>>5] = mx;
    __syncthreads();
    mx = red[0];
    #pragma unroll
    for (int i=1;i<8;i++) mx = fmaxf(mx, red[i]);

    v.x = __expf(v.x-mx); v.y = __expf(v.y-mx);
    v.z = __expf(v.z-mx); v.w = __expf(v.w-mx);
    float sum = (v.x+v.y)+(v.z+v.w);
    #pragma unroll
    for (int o=16;o;o>>=1) sum += __shfl_xor_sync(0xffffffffu, sum, o);
    if ((t&31)==0) red[8+(t>>5)] = sum;
    __syncthreads();
    sum = 0.f;
    #pragma unroll
    for (int i=0;i<8;i++) sum += red[8+i];

    float inv = 1.0f/sum;
    v.x*=inv; v.y*=inv; v.z*=inv; v.w*=inv;
    *(float4*)(p + t*4) = v;
}

// ---------------------------------------------------------------------------
// Kernel 4: context^T[d,kpos] = sum_q V[q,d] * A[q,kpos]  (single tf32)
// block tile m=64(d) x n=128(kpos), warps 2x4, warp 32x32; operands k-major
// ---------------------------------------------------------------------------
__global__ __launch_bounds__(256) void context_kernel(const float* __restrict__ attn){
    __shared__ float Vs[32][68];     // [q][d]
    __shared__ float As[32][132];    // [q][kpos]
    int tid = threadIdx.x;
    int nb = blockIdx.x*128, bh = blockIdx.y;
    int w = tid>>5, wm = w>>2, wn = w&3;
    int lane = tid&31, gr = lane>>2, c2 = (lane&3)*2;
    const float* Ag = attn + (size_t)bh*SEQ*SEQ + nb;
    const float* Vg = g_v + (size_t)bh*SEQ*HD;

    float acc[2][4][4] = {};
    for (int q0=0; q0<SEQ; q0+=32){
        __syncthreads();
        #pragma unroll
        for (int i=0;i<4;i++){ int lin=tid+i*256; int r=lin>>5, cc=(lin&31)*4;
            *(float4*)&As[r][cc] = *(const float4*)(Ag + (size_t)(q0+r)*SEQ + cc); }
        #pragma unroll
        for (int i=0;i<2;i++){ int lin=tid+i*256; int r=lin>>4, cc=(lin&15)*4;
            *(float4*)&Vs[r][cc] = *(const float4*)(Vg + (size_t)(q0+r)*HD + cc); }
        __syncthreads();
        #pragma unroll
        for (int kc=0; kc<32; kc+=8){
            uint32_t a_[2][4];
            #pragma unroll
            for (int mi=0;mi<2;mi++){
                float af[4]; lda4T(&Vs[0][0],68, wm*32+mi*16, kc, af);
                #pragma unroll
                for (int j=0;j<4;j++) a_[mi][j] = f2tf(af[j]);
            }
            #pragma unroll
            for (int ni=0;ni<4;ni++){
                float bf[2]; uint32_t b_[2];
                ldb2T(&As[0][0],132, wn*32+ni*8, kc, bf);
                b_[0]=f2tf(bf[0]); b_[1]=f2tf(bf[1]);
                #pragma unroll
                for (int mi=0;mi<2;mi++) mma8(acc[mi][ni], a_[mi], b_);
            }
        }
    }
    float* Cb = g_ctx + (size_t)bh*SEQ*HD;
    #pragma unroll
    for (int mi=0;mi<2;mi++)
    #pragma unroll
    for (int ni=0;ni<4;ni++){
        int drow = wm*32 + mi*16 + gr;
        int col  = nb + wn*32 + ni*8 + c2;
        Cb[(size_t)col*HD + drow]        = acc[mi][ni][0];
        Cb[(size_t)(col+1)*HD + drow]    = acc[mi][ni][1];
        Cb[(size_t)col*HD + drow+8]      = acc[mi][ni][2];
        Cb[(size_t)(col+1)*HD + drow+8]  = acc[mi][ni][3];
    }
}

// ---------------------------------------------------------------------------
// Kernel 5: output = ctx_flat @ wp^T + bp   (single tf32)
// block 128m x 64n, warps 4x2
// ---------------------------------------------------------------------------
__global__ __launch_bounds__(256) void outproj_kernel(const float* __restrict__ W,
        const float* __restrict__ bias, float* __restrict__ out){
    __shared__ float Cs[128][36];
    __shared__ float Ws[64][36];
    int tid = threadIdx.x;
    int m0 = blockIdx.x*128;
    int b = m0>>10, l0 = m0&1023;
    int w = tid>>5, wm = w>>1, wn = w&1;
    int lane = tid&31, gr = lane>>2, c2 = (lane&3)*2;

    float acc[2][4][4] = {};
    for (int k0=0; k0<QDIM; k0+=32){
        int h = k0>>6, off = k0&63;
        const float* Cg = g_ctx + ((size_t)(b*NH+h)*SEQ + l0)*HD + off;
        __syncthreads();
        #pragma unroll
        for (int i=0;i<4;i++){ int lin=tid+i*256; int r=lin>>3, cc=(lin&7)*4;
            *(float4*)&Cs[r][cc] = *(const float4*)(Cg + (size_t)r*HD + cc); }
        #pragma unroll
        for (int i=0;i<2;i++){ int lin=tid+i*256; int r=lin>>3, cc=(lin&7)*4;
            *(float4*)&Ws[r][cc] = *(const float4*)(W + (size_t)r*QDIM + k0 + cc); }
        __syncthreads();
        #pragma unroll
        for (int kc=0; kc<32; kc+=8){
            uint32_t a_[2][4];
            #pragma unroll
            for (int mi=0;mi<2;mi++){
                float af[4]; lda4(&Cs[0][0],36, wm*32+mi*16, kc, af);
                #pragma unroll
                for (int j=0;j<4;j++) a_[mi][j] = f2tf(af[j]);
            }
            #pragma unroll
            for (int ni=0;ni<4;ni++){
                float bf[2]; uint32_t b_[2];
                ldb2(&Ws[0][0],36, wn*32+ni*8, kc, bf);
                b_[0]=f2tf(bf[0]); b_[1]=f2tf(bf[1]);
                #pragma unroll
                for (int mi=0;mi<2;mi++) mma8(acc[mi][ni], a_[mi], b_);
            }
        }
    }
    #pragma unroll
    for (int mi=0;mi<2;mi++)
    #pragma unroll
    for (int ni=0;ni<4;ni++){
        int row = m0 + wm*32 + mi*16 + gr;
        int col = wn*32 + ni*8 + c2;
        float2 bb = *(const float2*)(bias + col);
        float2 v0 = {acc[mi][ni][0]+bb.x, acc[mi][ni][1]+bb.y};
        float2 v1 = {acc[mi][ni][2]+bb.x, acc[mi][ni][3]+bb.y};
        *(float2*)(out + (size_t)row*HD + col) = v0;
        *(float2*)(out + (size_t)(row+8)*HD + col) = v1;
    }
}

// ---------------------------------------------------------------------------
extern "C" void kernel_launch(void* const* d_in, const int* in_sizes, int n_in,
                              void* d_out, int out_size) {
    const float* q  = (const float*)d_in[0];
    const float* k  = (const float*)d_in[1];
    const float* v  = (const float*)d_in[2];
    const float* wq = (const float*)d_in[3];
    const float* bq = (const float*)d_in[4];
    const float* wk = (const float*)d_in[5];
    const float* bk = (const float*)d_in[6];
    const float* wv = (const float*)d_in[7];
    const float* bv = (const float*)d_in[8];
    const float* wp = (const float*)d_in[9];
    const float* bp = (const float*)d_in[10];

    float* out  = (float*)d_out;
    float* attn = out + OUT_ELEMS;

    dim3 projGrid(NH, (BATCH*SEQ)/128);          // (8, 32)
    proj_kernel<<<projGrid, 256>>>(q,  wq, bq, 0);
    proj_kernel<<<projGrid, 256>>>(k,  wk, bk, 1);
    proj_kernel<<<projGrid, 256>>>(v,  wv, bv, 2);

    dim3 scoreGrid(SEQ/128, SEQ/128, BATCH*NH);  // (8, 8, 32)
    scores_kernel<<<scoreGrid, 256>>>(attn);

    softmax_kernel<<<BATCH*NH*SEQ, 256>>>(attn);

    dim3 ctxGrid(SEQ/128, BATCH*NH);             // (8, 32)
    context_kernel<<<ctxGrid, 256>>>(attn);

    outproj_kernel<<<(BATCH*SEQ)/128, 256>>>(wp, bp, out);
}

// round 3
// speedup vs baseline: 1.6897x; 1.0359x over previous
#include <cuda_runtime.h>
#include <math.h>
#include <stdint.h>

#define BATCH 4
#define SEQ   1024
#define QDIM  512
#define NH    8
#define HD    64
#define BH    (BATCH*NH)
#define OUT_ELEMS  (BATCH*SEQ*HD)
#define PROJ_ELEMS (BATCH*NH*SEQ*HD)
#define NROWS (BH*SEQ)            // 32768 attn rows

__device__ float g_q[PROJ_ELEMS];
__device__ float g_k[PROJ_ELEMS];
__device__ float g_v[PROJ_ELEMS];
__device__ float g_ctx[PROJ_ELEMS];
__device__ float g_partial[NROWS * 8];
__device__ float g_rinv[NROWS];

// ---------------------------------------------------------------------------
// tf32 helpers
// ---------------------------------------------------------------------------
__device__ __forceinline__ uint32_t f2tf(float x){
    uint32_t r; asm("cvt.rna.tf32.f32 %0, %1;" : "=r"(r) : "f"(x)); return r;
}
__device__ __forceinline__ float tfr(float x){ return __uint_as_float(f2tf(x)); }
__device__ __forceinline__ void split_tf(float x, uint32_t& hi, uint32_t& lo){
    hi = f2tf(x);
    lo = f2tf(x - __uint_as_float(hi));
}
__device__ __forceinline__ void mma8(float c[4], const uint32_t a[4], const uint32_t b[2]){
    asm volatile("mma.sync.aligned.m16n8k8.row.col.f32.tf32.tf32.f32 "
        "{%0,%1,%2,%3},{%4,%5,%6,%7},{%8,%9},{%0,%1,%2,%3};"
        : "+f"(c[0]),"+f"(c[1]),"+f"(c[2]),"+f"(c[3])
        : "r"(a[0]),"r"(a[1]),"r"(a[2]),"r"(a[3]),"r"(b[0]),"r"(b[1]));
}

// fragment loaders (float smem, values already tf32-rounded where applicable)
__device__ __forceinline__ void lda4(const float* S, int stride, int row0, int kc, float a[4]){
    int lane = threadIdx.x & 31; int gr = lane>>2, c = lane&3;
    const float* p = S + (row0+gr)*stride + kc + c;
    a[0]=p[0]; a[1]=p[8*stride]; a[2]=p[4]; a[3]=p[8*stride+4];
}
__device__ __forceinline__ void ldb2(const float* S, int stride, int n0, int kc, float b[2]){
    int lane = threadIdx.x & 31;
    const float* p = S + (n0+(lane>>2))*stride + kc + (lane&3);
    b[0]=p[0]; b[1]=p[4];
}
__device__ __forceinline__ void lda4u(const float* S, int stride, int row0, int kc, uint32_t a[4]){
    int lane = threadIdx.x & 31; int gr = lane>>2, c = lane&3;
    const float* p = S + (row0+gr)*stride + kc + c;
    a[0]=__float_as_uint(p[0]); a[1]=__float_as_uint(p[8*stride]);
    a[2]=__float_as_uint(p[4]); a[3]=__float_as_uint(p[8*stride+4]);
}
__device__ __forceinline__ void ldb2u(const float* S, int stride, int n0, int kc, uint32_t b[2]){
    int lane = threadIdx.x & 31;
    const float* p = S + (n0+(lane>>2))*stride + kc + (lane&3);
    b[0]=__float_as_uint(p[0]); b[1]=__float_as_uint(p[4]);
}
__device__ __forceinline__ void lda4T(const float* S, int stride, int row0, int kc, float a[4]){
    int lane = threadIdx.x & 31; int gr = lane>>2, c = lane&3;
    const float* p = S + (kc+c)*stride + row0 + gr;
    a[0]=p[0]; a[1]=p[8]; a[2]=p[4*stride]; a[3]=p[4*stride+8];
}
__device__ __forceinline__ void ldb2T(const float* S, int stride, int n0, int kc, float b[2]){
    int lane = threadIdx.x & 31;
    const float* p = S + (kc+(lane&3))*stride + n0 + (lane>>2);
    b[0]=p[0]; b[1]=p[4*stride];
}

// ---------------------------------------------------------------------------
// Kernel 1: all three projections  Y = X @ W^T + b  (3xTF32) -> [b,h,l,d]
// grid (8 heads, 32 m-tiles, 3 sel), 256 threads, block tile 128m x 64n
// ---------------------------------------------------------------------------
__global__ __launch_bounds__(256) void proj_all_kernel(
        const float* __restrict__ x0, const float* __restrict__ x1, const float* __restrict__ x2,
        const float* __restrict__ w0, const float* __restrict__ w1, const float* __restrict__ w2,
        const float* __restrict__ b0, const float* __restrict__ b1, const float* __restrict__ b2){
    __shared__ float Xs[128][36];
    __shared__ float Ws[64][36];
    int sel = blockIdx.z;
    const float* X = sel==0 ? x0 : sel==1 ? x1 : x2;
    const float* W = sel==0 ? w0 : sel==1 ? w1 : w2;
    const float* bias = sel==0 ? b0 : sel==1 ? b1 : b2;
    float* dst = sel==0 ? g_q : sel==1 ? g_k : g_v;

    int tid = threadIdx.x;
    int h = blockIdx.x, n0 = h*64;
    int m0 = blockIdx.y*128;
    int w = tid>>5, wm = w>>1, wn = w&1;
    int lane = tid&31, gr = lane>>2, c2 = (lane&3)*2;

    float acc[2][4][4] = {};
    for (int k0=0; k0<QDIM; k0+=32){
        __syncthreads();
        #pragma unroll
        for (int i=0;i<4;i++){ int lin=tid+i*256; int r=lin>>3, cc=(lin&7)*4;
            *(float4*)&Xs[r][cc] = *(const float4*)(X + (size_t)(m0+r)*QDIM + k0 + cc); }
        #pragma unroll
        for (int i=0;i<2;i++){ int lin=tid+i*256; int r=lin>>3, cc=(lin&7)*4;
            *(float4*)&Ws[r][cc] = *(const float4*)(W + (size_t)(n0+r)*QDIM + k0 + cc); }
        __syncthreads();
        #pragma unroll
        for (int kc=0; kc<32; kc+=8){
            uint32_t ah[2][4], al[2][4];
            #pragma unroll
            for (int mi=0;mi<2;mi++){
                float af[4]; lda4(&Xs[0][0],36, wm*32+mi*16, kc, af);
                #pragma unroll
                for (int j=0;j<4;j++) split_tf(af[j], ah[mi][j], al[mi][j]);
            }
            #pragma unroll
            for (int ni=0;ni<4;ni++){
                float bf[2]; uint32_t bh_[2], bl_[2];
                ldb2(&Ws[0][0],36, wn*32+ni*8, kc, bf);
                split_tf(bf[0],bh_[0],bl_[0]); split_tf(bf[1],bh_[1],bl_[1]);
                #pragma unroll
                for (int mi=0;mi<2;mi++){
                    mma8(acc[mi][ni], ah[mi], bh_);
                    mma8(acc[mi][ni], ah[mi], bl_);
                    mma8(acc[mi][ni], al[mi], bh_);
                }
            }
        }
    }
    int b = m0>>10, l0 = m0&1023;
    float* base = dst + (size_t)(b*NH+h)*SEQ*HD;
    #pragma unroll
    for (int mi=0;mi<2;mi++)
    #pragma unroll
    for (int ni=0;ni<4;ni++){
        int row = l0 + wm*32 + mi*16 + gr;
        int col = wn*32 + ni*8 + c2;
        float2 bb = *(const float2*)(bias + n0 + col);
        float2 v0 = {acc[mi][ni][0]+bb.x, acc[mi][ni][1]+bb.y};
        float2 v1 = {acc[mi][ni][2]+bb.x, acc[mi][ni][3]+bb.y};
        *(float2*)(base + (size_t)row*HD + col) = v0;
        *(float2*)(base + (size_t)(row+8)*HD + col) = v1;
    }
}

// ---------------------------------------------------------------------------
// Kernel 2: P = exp(0.5 * Q K^T) (3xTF32, hi/lo pre-split into smem)
// -> attn region (unnormalized), + deterministic per-block row sums
// grid (8 kb, 8 qb, 32 bh), 512 threads, block tile 128q x 128k, warp 32x32
// ---------------------------------------------------------------------------
__global__ __launch_bounds__(512) void scores_exp_kernel(float* __restrict__ attn){
    extern __shared__ float sm[];
    float* Qhi = sm;
    float* Qlo = sm + 128*36;
    float* Khi = sm + 2*128*36;
    float* Klo = sm + 3*128*36;
    float (*sums)[4] = (float(*)[4])(sm + 4*128*36);

    int tid = threadIdx.x;
    int kb = blockIdx.x, q0b = blockIdx.y*128, bh = blockIdx.z;
    int w = tid>>5, wq = w>>2, wk = w&3;
    int lane = tid&31, gr = lane>>2, c2 = (lane&3)*2;
    const float* Qg = g_q + (size_t)(bh*SEQ + q0b)*HD;
    const float* Kg = g_k + (size_t)(bh*SEQ + kb*128)*HD;

    float acc[2][4][4] = {};
    #pragma unroll
    for (int dt=0; dt<2; dt++){
        int d0 = dt*32;
        __syncthreads();
        #pragma unroll
        for (int i=0;i<2;i++){
            int idx = tid + i*512;
            int r = idx>>3, cc = (idx&7)*4;
            float4 xq = *(const float4*)(Qg + (size_t)r*HD + d0 + cc);
            float4 xk = *(const float4*)(Kg + (size_t)r*HD + d0 + cc);
            float4 h, l;
            h.x=tfr(xq.x); l.x=tfr(xq.x-h.x); h.y=tfr(xq.y); l.y=tfr(xq.y-h.y);
            h.z=tfr(xq.z); l.z=tfr(xq.z-h.z); h.w=tfr(xq.w); l.w=tfr(xq.w-h.w);
            *(float4*)(Qhi + r*36 + cc) = h;
            *(float4*)(Qlo + r*36 + cc) = l;
            h.x=tfr(xk.x); l.x=tfr(xk.x-h.x); h.y=tfr(xk.y); l.y=tfr(xk.y-h.y);
            h.z=tfr(xk.z); l.z=tfr(xk.z-h.z); h.w=tfr(xk.w); l.w=tfr(xk.w-h.w);
            *(float4*)(Khi + r*36 + cc) = h;
            *(float4*)(Klo + r*36 + cc) = l;
        }
        __syncthreads();
        #pragma unroll
        for (int kc=0; kc<32; kc+=8){
            uint32_t ah[2][4], al[2][4];
            #pragma unroll
            for (int mi=0;mi<2;mi++){
                lda4u(Qhi,36, wq*32+mi*16, kc, ah[mi]);
                lda4u(Qlo,36, wq*32+mi*16, kc, al[mi]);
            }
            #pragma unroll
            for (int ni=0;ni<4;ni++){
                uint32_t bh_[2], bl_[2];
                ldb2u(Khi,36, wk*32+ni*8, kc, bh_);
                ldb2u(Klo,36, wk*32+ni*8, kc, bl_);
                #pragma unroll
                for (int mi=0;mi<2;mi++){
                    mma8(acc[mi][ni], ah[mi], bh_);
                    mma8(acc[mi][ni], ah[mi], bl_);
                    mma8(acc[mi][ni], al[mi], bh_);
                }
            }
        }
    }

    // epilogue: exp, write P, accumulate row sums
    float* Ab = attn + (size_t)bh*SEQ*SEQ;
    float rs[2][2] = {};
    #pragma unroll
    for (int mi=0;mi<2;mi++)
    #pragma unroll
    for (int ni=0;ni<4;ni++){
        float e0 = __expf(acc[mi][ni][0]*0.5f);
        float e1 = __expf(acc[mi][ni][1]*0.5f);
        float e2 = __expf(acc[mi][ni][2]*0.5f);
        float e3 = __expf(acc[mi][ni][3]*0.5f);
        int row = q0b + wq*32 + mi*16 + gr;
        int col = kb*128 + wk*32 + ni*8 + c2;
        float2 v0 = {e0, e1}, v1 = {e2, e3};
        *(float2*)(Ab + (size_t)row*SEQ + col) = v0;
        *(float2*)(Ab + (size_t)(row+8)*SEQ + col) = v1;
        rs[mi][0] += e0 + e1;
        rs[mi][1] += e2 + e3;
    }
    #pragma unroll
    for (int mi=0;mi<2;mi++)
    #pragma unroll
    for (int j=0;j<2;j++){
        float s = rs[mi][j];
        s += __shfl_xor_sync(0xffffffffu, s, 1);
        s += __shfl_xor_sync(0xffffffffu, s, 2);
        rs[mi][j] = s;
    }
    if ((lane&3)==0){
        #pragma unroll
        for (int mi=0;mi<2;mi++)
        #pragma unroll
        for (int j=0;j<2;j++)
            sums[wq*32 + mi*16 + gr + j*8][wk] = rs[mi][j];
    }
    __syncthreads();
    if (tid < 128){
        float t = sums[tid][0] + sums[tid][1] + sums[tid][2] + sums[tid][3];
        g_partial[(((size_t)bh*SEQ + q0b + tid)<<3) + kb] = t;
    }
}

// ---------------------------------------------------------------------------
// Kernel 3: row-sum reduce -> 1/S  (deterministic, fixed order)
// ---------------------------------------------------------------------------
__global__ __launch_bounds__(256) void rowsum_kernel(){
    int r = blockIdx.x*256 + threadIdx.x;
    const float* p = g_partial + ((size_t)r<<3);
    float s = ((p[0]+p[1])+(p[2]+p[3])) + ((p[4]+p[5])+(p[6]+p[7]));
    g_rinv[r] = 1.0f / s;
}

// ---------------------------------------------------------------------------
// Kernel 4: normalize attn in place + context^T[d,kpos] = sum_q A V
// grid (8 n-tiles, 32 bh), 256 threads
// ---------------------------------------------------------------------------
__global__ __launch_bounds__(256) void context_norm_kernel(float* __restrict__ attn){
    __shared__ float Vs[32][68];     // [q][d]
    __shared__ float As[32][132];    // [q][kpos] (normalized)
    int tid = threadIdx.x;
    int nb = blockIdx.x*128, bh = blockIdx.y;
    int w = tid>>5, wm = w>>2, wn = w&3;
    int lane = tid&31, gr = lane>>2, c2 = (lane&3)*2;
    float* Ag = attn + (size_t)bh*SEQ*SEQ + nb;
    const float* Vg = g_v + (size_t)bh*SEQ*HD;
    const float* rinv = g_rinv + (size_t)bh*SEQ;

    float acc[2][4][4] = {};
    for (int q0=0; q0<SEQ; q0+=32){
        __syncthreads();
        #pragma unroll
        for (int i=0;i<4;i++){
            int lin=tid+i*256; int r=lin>>5, cc=(lin&31)*4;
            float4 v = *(const float4*)(Ag + (size_t)(q0+r)*SEQ + cc);
            float inv = rinv[q0+r];
            v.x*=inv; v.y*=inv; v.z*=inv; v.w*=inv;
            *(float4*)&As[r][cc] = v;
            *(float4*)(Ag + (size_t)(q0+r)*SEQ + cc) = v;   // final attn
        }
        #pragma unroll
        for (int i=0;i<2;i++){ int lin=tid+i*256; int r=lin>>4, cc=(lin&15)*4;
            *(float4*)&Vs[r][cc] = *(const float4*)(Vg + (size_t)(q0+r)*HD + cc); }
        __syncthreads();
        #pragma unroll
        for (int kc=0; kc<32; kc+=8){
            uint32_t a_[2][4];
            #pragma unroll
            for (int mi=0;mi<2;mi++){
                float af[4]; lda4T(&Vs[0][0],68, wm*32+mi*16, kc, af);
                #pragma unroll
                for (int j=0;j<4;j++) a_[mi][j] = f2tf(af[j]);
            }
            #pragma unroll
            for (int ni=0;ni<4;ni++){
                float bf[2]; uint32_t b_[2];
                ldb2T(&As[0][0],132, wn*32+ni*8, kc, bf);
                b_[0]=f2tf(bf[0]); b_[1]=f2tf(bf[1]);
                #pragma unroll
                for (int mi=0;mi<2;mi++) mma8(acc[mi][ni], a_[mi], b_);
            }
        }
    }
    float* Cb = g_ctx + (size_t)bh*SEQ*HD;
    #pragma unroll
    for (int mi=0;mi<2;mi++)
    #pragma unroll
    for (int ni=0;ni<4;ni++){
        int drow = wm*32 + mi*16 + gr;
        int col  = nb + wn*32 + ni*8 + c2;
        Cb[(size_t)col*HD + drow]        = acc[mi][ni][0];
        Cb[(size_t)(col+1)*HD + drow]    = acc[mi][ni][1];
        Cb[(size_t)col*HD + drow+8]      = acc[mi][ni][2];
        Cb[(size_t)(col+1)*HD + drow+8]  = acc[mi][ni][3];
    }
}

// ---------------------------------------------------------------------------
// Kernel 5: output = ctx_flat @ wp^T + bp   (single tf32)
// ---------------------------------------------------------------------------
__global__ __launch_bounds__(256) void outproj_kernel(const float* __restrict__ W,
        const float* __restrict__ bias, float* __restrict__ out){
    __shared__ float Cs[128][36];
    __shared__ float Ws[64][36];
    int tid = threadIdx.x;
    int m0 = blockIdx.x*128;
    int b = m0>>10, l0 = m0&1023;
    int w = tid>>5, wm = w>>1, wn = w&1;
    int lane = tid&31, gr = lane>>2, c2 = (lane&3)*2;

    float acc[2][4][4] = {};
    for (int k0=0; k0<QDIM; k0+=32){
        int h = k0>>6, off = k0&63;
        const float* Cg = g_ctx + ((size_t)(b*NH+h)*SEQ + l0)*HD + off;
        __syncthreads();
        #pragma unroll
        for (int i=0;i<4;i++){ int lin=tid+i*256; int r=lin>>3, cc=(lin&7)*4;
            *(float4*)&Cs[r][cc] = *(const float4*)(Cg + (size_t)r*HD + cc); }
        #pragma unroll
        for (int i=0;i<2;i++){ int lin=tid+i*256; int r=lin>>3, cc=(lin&7)*4;
            *(float4*)&Ws[r][cc] = *(const float4*)(W + (size_t)r*QDIM + k0 + cc); }
        __syncthreads();
        #pragma unroll
        for (int kc=0; kc<32; kc+=8){
            uint32_t a_[2][4];
            #pragma unroll
            for (int mi=0;mi<2;mi++){
                float af[4]; lda4(&Cs[0][0],36, wm*32+mi*16, kc, af);
                #pragma unroll
                for (int j=0;j<4;j++) a_[mi][j] = f2tf(af[j]);
            }
            #pragma unroll
            for (int ni=0;ni<4;ni++){
                float bf[2]; uint32_t b_[2];
                ldb2(&Ws[0][0],36, wn*32+ni*8, kc, bf);
                b_[0]=f2tf(bf[0]); b_[1]=f2tf(bf[1]);
                #pragma unroll
                for (int mi=0;mi<2;mi++) mma8(acc[mi][ni], a_[mi], b_);
            }
        }
    }
    #pragma unroll
    for (int mi=0;mi<2;mi++)
    #pragma unroll
    for (int ni=0;ni<4;ni++){
        int row = m0 + wm*32 + mi*16 + gr;
        int col = wn*32 + ni*8 + c2;
        float2 bb = *(const float2*)(bias + col);
        float2 v0 = {acc[mi][ni][0]+bb.x, acc[mi][ni][1]+bb.y};
        float2 v1 = {acc[mi][ni][2]+bb.x, acc[mi][ni][3]+bb.y};
        *(float2*)(out + (size_t)row*HD + col) = v0;
        *(float2*)(out + (size_t)(row+8)*HD + col) = v1;
    }
}

// ---------------------------------------------------------------------------
extern "C" void kernel_launch(void* const* d_in, const int* in_sizes, int n_in,
                              void* d_out, int out_size) {
    const float* q  = (const float*)d_in[0];
    const float* k  = (const float*)d_in[1];
    const float* v  = (const float*)d_in[2];
    const float* wq = (const float*)d_in[3];
    const float* bq = (const float*)d_in[4];
    const float* wk = (const float*)d_in[5];
    const float* bk = (const float*)d_in[6];
    const float* wv = (const float*)d_in[7];
    const float* bv = (const float*)d_in[8];
    const float* wp = (const float*)d_in[9];
    const float* bp = (const float*)d_in[10];

    float* out  = (float*)d_out;
    float* attn = out + OUT_ELEMS;

    static int smem_set = 0;
    const int SCORES_SMEM = (4*128*36 + 128*4) * 4;   // 75776 B
    if (!smem_set){
        cudaFuncSetAttribute(scores_exp_kernel,
            cudaFuncAttributeMaxDynamicSharedMemorySize, SCORES_SMEM);
        smem_set = 1;
    }

    dim3 projGrid(NH, (BATCH*SEQ)/128, 3);            // (8, 32, 3)
    proj_all_kernel<<<projGrid, 256>>>(q, k, v, wq, wk, wv, bq, bk, bv);

    dim3 scoreGrid(SEQ/128, SEQ/128, BH);             // (8, 8, 32)
    scores_exp_kernel<<<scoreGrid, 512, SCORES_SMEM>>>(attn);

    rowsum_kernel<<<NROWS/256, 256>>>();

    dim3 ctxGrid(SEQ/128, BH);                        // (8, 32)
    context_norm_kernel<<<ctxGrid, 256>>>(attn);

    outproj_kernel<<<(BATCH*SEQ)/128, 256>>>(wp, bp, out);
}